// round 15
// baseline (speedup 1.0000x reference)
#include <cuda_runtime.h>
#include <cstdint>

// Problem constants (fixed by the reference):
//   BATCH*SEQ = 65536 tokens, HIDDEN = 768, 8 hashes x 16384 buckets x 96-float shards.
#define NUM_HASHES   8
#define NUM_BUCKETS  16384
#define SHARD        96
#define HIDDEN       768
#define LN_EPS       1e-6f

// Primes {31,43,59,61,73,97,103,113} packed as little-endian bytes.
#define PACKED_PRIMES 0x716761493D3B2B1Full

// TWO warps per token (64 threads/token, 4 tokens per 256-thread block).
// Each lane owns 3 float4s (12 regs of values vs 24 in the 1-warp layout),
// cutting the register footprint so 8 blocks (64 warps) fit per SM.
// Cross-warp LN reduction via 64B of smem + one barrier.
// Single kernel: the trivial-affine check (scale==1, bias==0, as the
// reference's setup_inputs produces) is re-verified per block every launch,
// so arbitrary scale/bias still gives correct output via the slow path.
__global__ __launch_bounds__(256, 8) void canine_emb_ln_kernel(
    const void*      __restrict__ ids_raw, // [n_tokens] int32 OR int64
    const float*     __restrict__ tables,  // [8, 16384, 96] f32
    const float*     __restrict__ ln_scale,// [768]
    const float*     __restrict__ ln_bias, // [768]
    float*           __restrict__ out,     // [n_tokens, 768]
    int n_tokens)
{
    __shared__ float2 s_part[8];   // per-warp (sum, sumsq) partials

    const float4* sc4 = reinterpret_cast<const float4*>(ln_scale);
    const float4* bi4 = reinterpret_cast<const float4*>(ln_bias);

    // --- per-block affine-trivial check (block-uniform flag) ---
    bool okc = true;
    for (int i = threadIdx.x; i < HIDDEN / 4; i += 256) {
        const float4 sc = __ldg(sc4 + i);
        const float4 bi = __ldg(bi4 + i);
        okc = okc && sc.x == 1.0f && sc.y == 1.0f && sc.z == 1.0f && sc.w == 1.0f
                  && bi.x == 0.0f && bi.y == 0.0f && bi.z == 0.0f && bi.w == 0.0f;
    }
    const int trivial = __syncthreads_and(okc ? 1 : 0);

    const int wid    = threadIdx.x >> 5;        // warp in block [0,8)
    const int lane   = threadIdx.x & 31;
    const int tid2   = threadIdx.x & 63;        // thread within token group
    const int token  = blockIdx.x * 4 + (threadIdx.x >> 6);
    const bool valid = token < n_tokens;

    // --- dtype detect: 32 aligned u64 words of the prefix (256B, in-bounds
    // for both interpretations; L1-hot broadcast). True int64 ids < 2^32 have
    // zero high words; packed int32 pairs have random nonzero high words.
    // (JAX with x64 disabled silently downgrades jnp.int64 randint to int32.)
    const unsigned long long probe =
        ((const unsigned long long*)ids_raw)[lane];
    const bool is64 = !__any_sync(0xFFFFFFFFu, probe > 0xFFFFFFFFull);

    // ids in [0, 1114112): (id+1)*prime fits in int32, result non-negative.
    int id = 0;
    if (valid) {
        if (is64) id = (int)((const long long*)ids_raw)[token];
        else      id = ((const int*)ids_raw)[token];
    }
    const int idp = id + 1;

    // Gather 3 float4s per lane. float4 index j = tid2 + 64*k in [0,192).
    // Hash shard h = j/24 (24 float4s per shard); reference hidden layout puts
    // hash h at columns [96h, 96h+96). Bucket computed inline (pure ALU).
    // Table float4 index: h*393216 + bucket*24 + (j-24h) = h*393192 + bkt*24 + j.
    const float4* t4 = reinterpret_cast<const float4*>(tables);
    float4 v[3];
    float s = 0.f, ss = 0.f;
    if (valid) {
#pragma unroll
        for (int k = 0; k < 3; k++) {
            const int j     = tid2 + 64 * k;
            const int h     = j / 24;
            const int prime = (int)((PACKED_PRIMES >> (h * 8)) & 0xFF);
            const int bkt   = (idp * prime) & (NUM_BUCKETS - 1);
            v[k] = __ldg(t4 + ((size_t)h * 393192 + (size_t)bkt * 24 + j));
        }
#pragma unroll
        for (int k = 0; k < 3; k++) {
            s  += v[k].x + v[k].y + v[k].z + v[k].w;
            ss += v[k].x * v[k].x + v[k].y * v[k].y
                + v[k].z * v[k].z + v[k].w * v[k].w;
        }
    }

    // Warp-level reduction of this warp's 384 values.
#pragma unroll
    for (int d = 16; d > 0; d >>= 1) {
        s  += __shfl_xor_sync(0xFFFFFFFFu, s,  d);
        ss += __shfl_xor_sync(0xFFFFFFFFu, ss, d);
    }
    if (lane == 0) s_part[wid] = make_float2(s, ss);
    __syncthreads();

    // Combine the two warps of this token.
    const int wbase = (wid & ~1);
    const float2 p0 = s_part[wbase];
    const float2 p1 = s_part[wbase + 1];
    const float sum_all = p0.x + p1.x;
    const float ssq_all = p0.y + p1.y;

    const float inv_n = 1.0f / (float)HIDDEN;
    const float mean  = sum_all * inv_n;
    const float var   = fmaxf(ssq_all * inv_n - mean * mean, 0.0f);
    const float rstd  = rsqrtf(var + LN_EPS);

    if (!valid) return;

    // Normalize (+ affine only if needed); streaming stores keep the tables
    // L2-resident while 201MB of output flows through.
    float4* o4 = reinterpret_cast<float4*>(out + (size_t)token * HIDDEN);

    if (trivial) {
        // Fast path: scale==1, bias==0 — no sc/bi loads in the hot loop.
#pragma unroll
        for (int k = 0; k < 3; k++) {
            const int j = tid2 + 64 * k;
            float4 r;
            r.x = (v[k].x - mean) * rstd;
            r.y = (v[k].y - mean) * rstd;
            r.z = (v[k].z - mean) * rstd;
            r.w = (v[k].w - mean) * rstd;
            __stcs(o4 + j, r);
        }
    } else {
#pragma unroll
        for (int k = 0; k < 3; k++) {
            const int j = tid2 + 64 * k;
            const float4 sc = __ldg(sc4 + j);
            const float4 bi = __ldg(bi4 + j);
            float4 r;
            r.x = (v[k].x - mean) * rstd * sc.x + bi.x;
            r.y = (v[k].y - mean) * rstd * sc.y + bi.y;
            r.z = (v[k].z - mean) * rstd * sc.z + bi.z;
            r.w = (v[k].w - mean) * rstd * sc.w + bi.w;
            __stcs(o4 + j, r);
        }
    }
}

extern "C" void kernel_launch(void* const* d_in, const int* in_sizes, int n_in,
                              void* d_out, int out_size)
{
    const void*  ids    = d_in[0];                 // int32 or int64 input_ids
    const float* tables = (const float*)d_in[1];   // [8,16384,96]
    const float* scale  = (const float*)d_in[2];   // [768]
    const float* bias   = (const float*)d_in[3];   // [768]
    float*       out    = (float*)d_out;

    const int n_tokens = in_sizes[0];              // BATCH*SEQ = 65536
    const int tokens_per_block = 4;                // 2 warps per token
    const int blocks = (n_tokens + tokens_per_block - 1) / tokens_per_block;
    canine_emb_ln_kernel<<<blocks, 256>>>(ids, tables, scale, bias, out, n_tokens);
}